// round 1
// baseline (speedup 1.0000x reference)
#include <cuda_runtime.h>
#include <math.h>

// ---------------------------------------------------------------------------
// GNN_16535624089969: 2-layer GCN (DGL GraphConv norm='both')
//   N=50000 nodes, E=800000 edges, dims 256 -> 128 -> 64, fp32.
// Strategy:
//   - degrees via int atomics, norms = rsqrt(max(deg,1))
//   - CSR by dst (histogram + 1-block scan + cursor scatter) -> atomic-free SpMM
//   - GEMM1 epilogue bakes in norm_src; layer-1 finalize bakes relu+b1+norm_src
//   - aggregation: one warp per node, float4 (layer1) / float2 (layer2) lanes
// ---------------------------------------------------------------------------

#define MAXN 50048
#define MAXE 800000
#define HID_DIM 128
#define OUT_DIM 64

__device__ float g_h1s[50000 * HID_DIM];   // (x@W1) * norm_src
__device__ float g_hs2[50000 * HID_DIM];   // relu(agg1*nd+b1) * norm_src
__device__ float g_g2 [50000 * OUT_DIM];   // hs2 @ W2  (already carries ns)
__device__ int   g_csr_src[MAXE];
__device__ int   g_row_ptr[MAXN + 1];
__device__ int   g_cursor[MAXN];
__device__ int   g_outdeg[MAXN];
__device__ int   g_indeg[MAXN];
__device__ float g_ns[MAXN];
__device__ float g_nd[MAXN];

// ---------------------------------------------------------------------------
__global__ void zero_kernel(int n) {
    int i = blockIdx.x * blockDim.x + threadIdx.x;
    if (i < n) {
        g_outdeg[i] = 0;
        g_indeg[i]  = 0;
        g_cursor[i] = 0;
    }
}

__global__ void deg_kernel(const int* __restrict__ src,
                           const int* __restrict__ dst, int E) {
    int e = blockIdx.x * blockDim.x + threadIdx.x;
    if (e < E) {
        atomicAdd(&g_outdeg[src[e]], 1);
        atomicAdd(&g_indeg[dst[e]], 1);
    }
}

__global__ void norm_kernel(int n) {
    int i = blockIdx.x * blockDim.x + threadIdx.x;
    if (i < n) {
        g_ns[i] = rsqrtf(fmaxf((float)g_outdeg[i], 1.0f));
        g_nd[i] = rsqrtf(fmaxf((float)g_indeg[i], 1.0f));
    }
}

// single-block exclusive scan of g_indeg -> g_row_ptr (n up to 50000)
__global__ void scan_kernel(int n) {
    __shared__ int sh[1024];
    __shared__ int offset;
    int tid = threadIdx.x;
    if (tid == 0) { offset = 0; g_row_ptr[0] = 0; }
    __syncthreads();
    for (int base = 0; base < n; base += 1024) {
        int v = (base + tid < n) ? g_indeg[base + tid] : 0;
        sh[tid] = v;
        __syncthreads();
        for (int d = 1; d < 1024; d <<= 1) {
            int t = (tid >= d) ? sh[tid - d] : 0;
            __syncthreads();
            sh[tid] += t;
            __syncthreads();
        }
        int cur = offset;
        if (base + tid < n) g_row_ptr[base + tid + 1] = cur + sh[tid];
        __syncthreads();
        if (tid == 0) offset = cur + sh[1023];
        __syncthreads();
    }
}

__global__ void csr_fill_kernel(const int* __restrict__ src,
                                const int* __restrict__ dst, int E) {
    int e = blockIdx.x * blockDim.x + threadIdx.x;
    if (e < E) {
        int d = dst[e];
        int pos = g_row_ptr[d] + atomicAdd(&g_cursor[d], 1);
        g_csr_src[pos] = src[e];
    }
}

// ---------------------------------------------------------------------------
// Tiled fp32 GEMM: C[M,N] = A[M,K] @ B[K,N], optional epilogue *= g_ns[row].
// 256 threads; (BM/TM)*(BN/TN) == 256; K % BK == 0; N == BN * gridDim.y(=1).
// ---------------------------------------------------------------------------
template <int BM, int BN, int BK, int TM, int TN, bool SCALE_NS>
__global__ __launch_bounds__(256)
void gemm_kernel(const float* __restrict__ A, const float* __restrict__ B,
                 float* __restrict__ C, int M, int N, int K) {
    __shared__ float As[BK][BM];
    __shared__ float Bs[BK][BN];

    const int tid = threadIdx.x;
    const int block_row = blockIdx.x * BM;
    constexpr int TCOLS = BN / TN;
    const int tcol = tid % TCOLS;
    const int trow = tid / TCOLS;

    float acc[TM][TN];
#pragma unroll
    for (int i = 0; i < TM; i++)
#pragma unroll
        for (int j = 0; j < TN; j++) acc[i][j] = 0.0f;

    for (int k0 = 0; k0 < K; k0 += BK) {
        // load A tile (transposed into As[BK][BM]) via float4
#pragma unroll
        for (int i = tid; i < BM * BK / 4; i += 256) {
            int r  = i / (BK / 4);
            int c4 = i % (BK / 4);
            int grow = block_row + r;
            float4 v = make_float4(0.f, 0.f, 0.f, 0.f);
            if (grow < M)
                v = *(const float4*)&A[(size_t)grow * K + k0 + c4 * 4];
            As[c4 * 4 + 0][r] = v.x;
            As[c4 * 4 + 1][r] = v.y;
            As[c4 * 4 + 2][r] = v.z;
            As[c4 * 4 + 3][r] = v.w;
        }
        // load B tile
#pragma unroll
        for (int i = tid; i < BK * BN / 4; i += 256) {
            int r  = i / (BN / 4);
            int c4 = i % (BN / 4);
            *(float4*)&Bs[r][c4 * 4] =
                *(const float4*)&B[(size_t)(k0 + r) * N + c4 * 4];
        }
        __syncthreads();

#pragma unroll
        for (int k = 0; k < BK; k++) {
            float a[TM];
            float4 b0 = *(const float4*)&Bs[k][tcol * TN];
            float b[TN] = {b0.x, b0.y, b0.z, b0.w};
#pragma unroll
            for (int i = 0; i < TM; i++) a[i] = As[k][trow * TM + i];
#pragma unroll
            for (int i = 0; i < TM; i++)
#pragma unroll
                for (int j = 0; j < TN; j++)
                    acc[i][j] = fmaf(a[i], b[j], acc[i][j]);
        }
        __syncthreads();
    }

#pragma unroll
    for (int i = 0; i < TM; i++) {
        int grow = block_row + trow * TM + i;
        if (grow >= M) continue;
        float s = 1.0f;
        if (SCALE_NS) s = g_ns[grow];
        float4 v;
        v.x = acc[i][0] * s;
        v.y = acc[i][1] * s;
        v.z = acc[i][2] * s;
        v.w = acc[i][3] * s;
        *(float4*)&C[(size_t)grow * N + tcol * TN] = v;
    }
}

// ---------------------------------------------------------------------------
// Layer-1 aggregation: warp per node over CSR, 128 feats = 32 lanes x float4.
// hs2[i] = relu(sum_j h1s[csr_src] * nd[i] + b1) * ns[i]
// ---------------------------------------------------------------------------
__global__ __launch_bounds__(256)
void agg1_kernel(const float* __restrict__ b1, int n) {
    int node = blockIdx.x * (blockDim.x >> 5) + (threadIdx.x >> 5);
    if (node >= n) return;
    int lane = threadIdx.x & 31;
    int s = g_row_ptr[node];
    int e = g_row_ptr[node + 1];
    float4 acc = make_float4(0.f, 0.f, 0.f, 0.f);
#pragma unroll 4
    for (int j = s; j < e; j++) {
        int u = g_csr_src[j];
        float4 v = *(const float4*)&g_h1s[(size_t)u * HID_DIM + lane * 4];
        acc.x += v.x; acc.y += v.y; acc.z += v.z; acc.w += v.w;
    }
    float nd = g_nd[node];
    float ns = g_ns[node];
    float4 bb = *(const float4*)&b1[lane * 4];
    float4 o;
    o.x = fmaxf(fmaf(acc.x, nd, bb.x), 0.f) * ns;
    o.y = fmaxf(fmaf(acc.y, nd, bb.y), 0.f) * ns;
    o.z = fmaxf(fmaf(acc.z, nd, bb.z), 0.f) * ns;
    o.w = fmaxf(fmaf(acc.w, nd, bb.w), 0.f) * ns;
    *(float4*)&g_hs2[(size_t)node * HID_DIM + lane * 4] = o;
}

// ---------------------------------------------------------------------------
// Layer-2 aggregation: warp per node, 64 feats = 32 lanes x float2.
// out[i] = sum_j g2[csr_src] * nd[i] + b2
// ---------------------------------------------------------------------------
__global__ __launch_bounds__(256)
void agg2_kernel(const float* __restrict__ b2, float* __restrict__ out, int n) {
    int node = blockIdx.x * (blockDim.x >> 5) + (threadIdx.x >> 5);
    if (node >= n) return;
    int lane = threadIdx.x & 31;
    int s = g_row_ptr[node];
    int e = g_row_ptr[node + 1];
    float2 acc = make_float2(0.f, 0.f);
#pragma unroll 4
    for (int j = s; j < e; j++) {
        int u = g_csr_src[j];
        float2 v = *(const float2*)&g_g2[(size_t)u * OUT_DIM + lane * 2];
        acc.x += v.x; acc.y += v.y;
    }
    float nd = g_nd[node];
    float2 bb = *(const float2*)&b2[lane * 2];
    float2 o;
    o.x = fmaf(acc.x, nd, bb.x);
    o.y = fmaf(acc.y, nd, bb.y);
    *(float2*)&out[(size_t)node * OUT_DIM + lane * 2] = o;
}

// ---------------------------------------------------------------------------
extern "C" void kernel_launch(void* const* d_in, const int* in_sizes, int n_in,
                              void* d_out, int out_size) {
    const float* x   = (const float*)d_in[0];
    const float* W1  = (const float*)d_in[1];
    const float* b1  = (const float*)d_in[2];
    const float* W2  = (const float*)d_in[3];
    const float* b2  = (const float*)d_in[4];
    const int*   src = (const int*)d_in[5];
    const int*   dst = (const int*)d_in[6];
    float* out = (float*)d_out;

    const int hid = in_sizes[2];            // 128
    const int od  = in_sizes[4];            // 64
    const int inf = in_sizes[1] / hid;      // 256
    const int n   = in_sizes[0] / inf;      // 50000
    const int E   = in_sizes[5];            // 800000

    float *p_h1s, *p_hs2, *p_g2;
    cudaGetSymbolAddress((void**)&p_h1s, g_h1s);
    cudaGetSymbolAddress((void**)&p_hs2, g_hs2);
    cudaGetSymbolAddress((void**)&p_g2,  g_g2);

    // graph structure
    zero_kernel<<<(n + 255) / 256, 256>>>(n);
    deg_kernel<<<(E + 255) / 256, 256>>>(src, dst, E);
    norm_kernel<<<(n + 255) / 256, 256>>>(n);
    scan_kernel<<<1, 1024>>>(n);
    csr_fill_kernel<<<(E + 255) / 256, 256>>>(src, dst, E);

    // layer 1: h1s = (x @ W1) * ns   (M=n, N=128, K=256)
    gemm_kernel<64, 128, 16, 8, 4, true>
        <<<(n + 63) / 64, 256>>>(x, W1, p_h1s, n, hid, inf);
    agg1_kernel<<<(n + 7) / 8, 256>>>(b1, n);

    // layer 2: g2 = hs2 @ W2   (M=n, N=64, K=128); ns already baked into hs2
    gemm_kernel<128, 64, 16, 8, 4, false>
        <<<(n + 127) / 128, 256>>>(p_hs2, W2, p_g2, n, od, hid);
    agg2_kernel<<<(n + 7) / 8, 256>>>(b2, out, n);
}

// round 2
// speedup vs baseline: 1.1830x; 1.1830x over previous
#include <cuda_runtime.h>
#include <math.h>

// ---------------------------------------------------------------------------
// GNN_16535624089969: 2-layer GCN (DGL GraphConv norm='both')
//   N=50000 nodes, E=800000 edges, dims 256 -> 128 -> 64, fp32.
// R1 changes:
//   - single-block O(n) scan (81.8us!) -> 3-phase multi-block shuffle scan (~4us)
//   - norm computation folded into scan phase 1
//   - GEMM1 tile 64x128 -> 128x128, TM=TN=8 (FMA:LDS 64:16 per k-step)
// ---------------------------------------------------------------------------

#define MAXN 50048
#define MAXE 800000
#define HID_DIM 128
#define OUT_DIM 64
#define SCAN_BLK 1024
#define MAX_SCAN_BLOCKS 64

__device__ float g_h1s[50000 * HID_DIM];   // (x@W1) * norm_src
__device__ float g_hs2[50000 * HID_DIM];   // relu(agg1*nd+b1) * norm_src
__device__ float g_g2 [50000 * OUT_DIM];   // hs2 @ W2  (already carries ns)
__device__ int   g_csr_src[MAXE];
__device__ int   g_row_ptr[MAXN + 1];
__device__ int   g_cursor[MAXN];
__device__ int   g_outdeg[MAXN];
__device__ int   g_indeg[MAXN];
__device__ float g_ns[MAXN];
__device__ float g_nd[MAXN];
__device__ int   g_block_sums[MAX_SCAN_BLOCKS];
__device__ int   g_block_off[MAX_SCAN_BLOCKS];

// ---------------------------------------------------------------------------
__global__ void zero_kernel(int n) {
    int i = blockIdx.x * blockDim.x + threadIdx.x;
    if (i < n) {
        g_outdeg[i] = 0;
        g_indeg[i]  = 0;
        g_cursor[i] = 0;
    }
}

__global__ void deg_kernel(const int* __restrict__ src,
                           const int* __restrict__ dst, int E) {
    int e = blockIdx.x * blockDim.x + threadIdx.x;
    if (e < E) {
        atomicAdd(&g_outdeg[src[e]], 1);
        atomicAdd(&g_indeg[dst[e]], 1);
    }
}

// ---------------------------------------------------------------------------
// Scan phase 1: per-block (1024 elems) inclusive scan of indeg via warp
// shuffles; writes local inclusive prefix to row_ptr[i+1], block total to
// g_block_sums. Also computes ns/nd norms (same element range).
// ---------------------------------------------------------------------------
__global__ __launch_bounds__(SCAN_BLK)
void scan1_kernel(int n) {
    int tid  = threadIdx.x;
    int i    = blockIdx.x * SCAN_BLK + tid;
    int lane = tid & 31;
    int w    = tid >> 5;

    int indeg = 0, outdeg = 0;
    if (i < n) {
        indeg  = g_indeg[i];
        outdeg = g_outdeg[i];
        g_ns[i] = rsqrtf(fmaxf((float)outdeg, 1.0f));
        g_nd[i] = rsqrtf(fmaxf((float)indeg, 1.0f));
    }

    // warp inclusive scan
    int s = indeg;
#pragma unroll
    for (int d = 1; d < 32; d <<= 1) {
        int t = __shfl_up_sync(0xffffffffu, s, d);
        if (lane >= d) s += t;
    }
    __shared__ int wsum[32];
    if (lane == 31) wsum[w] = s;
    __syncthreads();
    if (w == 0) {
        int x = wsum[lane];
#pragma unroll
        for (int d = 1; d < 32; d <<= 1) {
            int t = __shfl_up_sync(0xffffffffu, x, d);
            if (lane >= d) x += t;
        }
        wsum[lane] = x;
    }
    __syncthreads();
    if (w > 0) s += wsum[w - 1];

    if (i < n) g_row_ptr[i + 1] = s;          // local inclusive prefix
    if (tid == SCAN_BLK - 1) g_block_sums[blockIdx.x] = s;
}

// Scan phase 2: exclusive scan of <=64 block sums, single block of 64.
__global__ void scan2_kernel(int nb) {
    __shared__ int sh[MAX_SCAN_BLOCKS];
    int tid = threadIdx.x;
    sh[tid] = (tid < nb) ? g_block_sums[tid] : 0;
    __syncthreads();
#pragma unroll
    for (int d = 1; d < MAX_SCAN_BLOCKS; d <<= 1) {
        int t = (tid >= d) ? sh[tid - d] : 0;
        __syncthreads();
        sh[tid] += t;
        __syncthreads();
    }
    if (tid < nb) g_block_off[tid] = (tid == 0) ? 0 : sh[tid - 1];
    if (tid == 0) g_row_ptr[0] = 0;
}

// Scan phase 3: add block offsets.
__global__ __launch_bounds__(SCAN_BLK)
void scan3_kernel(int n) {
    int i = blockIdx.x * SCAN_BLK + threadIdx.x;
    if (i < n && blockIdx.x > 0) g_row_ptr[i + 1] += g_block_off[blockIdx.x];
}

__global__ void csr_fill_kernel(const int* __restrict__ src,
                                const int* __restrict__ dst, int E) {
    int e = blockIdx.x * blockDim.x + threadIdx.x;
    if (e < E) {
        int d = dst[e];
        int pos = g_row_ptr[d] + atomicAdd(&g_cursor[d], 1);
        g_csr_src[pos] = src[e];
    }
}

// ---------------------------------------------------------------------------
// Tiled fp32 GEMM: C[M,N] = A[M,K] @ B[K,N], optional epilogue *= g_ns[row].
// 256 threads; (BM/TM)*(BN/TN) == 256; K % BK == 0; N == BN.
// ---------------------------------------------------------------------------
template <int BM, int BN, int BK, int TM, int TN, bool SCALE_NS>
__global__ __launch_bounds__(256)
void gemm_kernel(const float* __restrict__ A, const float* __restrict__ B,
                 float* __restrict__ C, int M, int N, int K) {
    __shared__ float As[BK][BM];
    __shared__ float Bs[BK][BN];

    const int tid = threadIdx.x;
    const int block_row = blockIdx.x * BM;
    constexpr int TCOLS = BN / TN;
    const int tcol = tid % TCOLS;
    const int trow = tid / TCOLS;

    float acc[TM][TN];
#pragma unroll
    for (int i = 0; i < TM; i++)
#pragma unroll
        for (int j = 0; j < TN; j++) acc[i][j] = 0.0f;

    for (int k0 = 0; k0 < K; k0 += BK) {
        // load A tile (transposed into As[BK][BM]) via float4
#pragma unroll
        for (int i = tid; i < BM * BK / 4; i += 256) {
            int r  = i / (BK / 4);
            int c4 = i % (BK / 4);
            int grow = block_row + r;
            float4 v = make_float4(0.f, 0.f, 0.f, 0.f);
            if (grow < M)
                v = *(const float4*)&A[(size_t)grow * K + k0 + c4 * 4];
            As[c4 * 4 + 0][r] = v.x;
            As[c4 * 4 + 1][r] = v.y;
            As[c4 * 4 + 2][r] = v.z;
            As[c4 * 4 + 3][r] = v.w;
        }
        // load B tile
#pragma unroll
        for (int i = tid; i < BK * BN / 4; i += 256) {
            int r  = i / (BN / 4);
            int c4 = i % (BN / 4);
            *(float4*)&Bs[r][c4 * 4] =
                *(const float4*)&B[(size_t)(k0 + r) * N + c4 * 4];
        }
        __syncthreads();

#pragma unroll
        for (int k = 0; k < BK; k++) {
            float a[TM];
            float b[TN];
#pragma unroll
            for (int j4 = 0; j4 < TN / 4; j4++) {
                float4 b0 = *(const float4*)&Bs[k][tcol * TN + j4 * 4];
                b[j4 * 4 + 0] = b0.x;
                b[j4 * 4 + 1] = b0.y;
                b[j4 * 4 + 2] = b0.z;
                b[j4 * 4 + 3] = b0.w;
            }
#pragma unroll
            for (int i = 0; i < TM; i++) a[i] = As[k][trow * TM + i];
#pragma unroll
            for (int i = 0; i < TM; i++)
#pragma unroll
                for (int j = 0; j < TN; j++)
                    acc[i][j] = fmaf(a[i], b[j], acc[i][j]);
        }
        __syncthreads();
    }

#pragma unroll
    for (int i = 0; i < TM; i++) {
        int grow = block_row + trow * TM + i;
        if (grow >= M) continue;
        float s = 1.0f;
        if (SCALE_NS) s = g_ns[grow];
#pragma unroll
        for (int j4 = 0; j4 < TN / 4; j4++) {
            float4 v;
            v.x = acc[i][j4 * 4 + 0] * s;
            v.y = acc[i][j4 * 4 + 1] * s;
            v.z = acc[i][j4 * 4 + 2] * s;
            v.w = acc[i][j4 * 4 + 3] * s;
            *(float4*)&C[(size_t)grow * N + tcol * TN + j4 * 4] = v;
        }
    }
}

// ---------------------------------------------------------------------------
// Layer-1 aggregation: warp per node over CSR, 128 feats = 32 lanes x float4.
// hs2[i] = relu(sum_j h1s[csr_src] * nd[i] + b1) * ns[i]
// ---------------------------------------------------------------------------
__global__ __launch_bounds__(256)
void agg1_kernel(const float* __restrict__ b1, int n) {
    int node = blockIdx.x * (blockDim.x >> 5) + (threadIdx.x >> 5);
    if (node >= n) return;
    int lane = threadIdx.x & 31;
    int s = g_row_ptr[node];
    int e = g_row_ptr[node + 1];
    float4 acc = make_float4(0.f, 0.f, 0.f, 0.f);
#pragma unroll 4
    for (int j = s; j < e; j++) {
        int u = g_csr_src[j];
        float4 v = *(const float4*)&g_h1s[(size_t)u * HID_DIM + lane * 4];
        acc.x += v.x; acc.y += v.y; acc.z += v.z; acc.w += v.w;
    }
    float nd = g_nd[node];
    float ns = g_ns[node];
    float4 bb = *(const float4*)&b1[lane * 4];
    float4 o;
    o.x = fmaxf(fmaf(acc.x, nd, bb.x), 0.f) * ns;
    o.y = fmaxf(fmaf(acc.y, nd, bb.y), 0.f) * ns;
    o.z = fmaxf(fmaf(acc.z, nd, bb.z), 0.f) * ns;
    o.w = fmaxf(fmaf(acc.w, nd, bb.w), 0.f) * ns;
    *(float4*)&g_hs2[(size_t)node * HID_DIM + lane * 4] = o;
}

// ---------------------------------------------------------------------------
// Layer-2 aggregation: warp per node, 64 feats = 32 lanes x float2.
// out[i] = sum_j g2[csr_src] * nd[i] + b2
// ---------------------------------------------------------------------------
__global__ __launch_bounds__(256)
void agg2_kernel(const float* __restrict__ b2, float* __restrict__ out, int n) {
    int node = blockIdx.x * (blockDim.x >> 5) + (threadIdx.x >> 5);
    if (node >= n) return;
    int lane = threadIdx.x & 31;
    int s = g_row_ptr[node];
    int e = g_row_ptr[node + 1];
    float2 acc = make_float2(0.f, 0.f);
#pragma unroll 4
    for (int j = s; j < e; j++) {
        int u = g_csr_src[j];
        float2 v = *(const float2*)&g_g2[(size_t)u * OUT_DIM + lane * 2];
        acc.x += v.x; acc.y += v.y;
    }
    float nd = g_nd[node];
    float2 bb = *(const float2*)&b2[lane * 2];
    float2 o;
    o.x = fmaf(acc.x, nd, bb.x);
    o.y = fmaf(acc.y, nd, bb.y);
    *(float2*)&out[(size_t)node * OUT_DIM + lane * 2] = o;
}

// ---------------------------------------------------------------------------
extern "C" void kernel_launch(void* const* d_in, const int* in_sizes, int n_in,
                              void* d_out, int out_size) {
    const float* x   = (const float*)d_in[0];
    const float* W1  = (const float*)d_in[1];
    const float* b1  = (const float*)d_in[2];
    const float* W2  = (const float*)d_in[3];
    const float* b2  = (const float*)d_in[4];
    const int*   src = (const int*)d_in[5];
    const int*   dst = (const int*)d_in[6];
    float* out = (float*)d_out;

    const int hid = in_sizes[2];            // 128
    const int od  = in_sizes[4];            // 64
    const int inf = in_sizes[1] / hid;      // 256
    const int n   = in_sizes[0] / inf;      // 50000
    const int E   = in_sizes[5];            // 800000

    float *p_h1s, *p_hs2, *p_g2;
    cudaGetSymbolAddress((void**)&p_h1s, g_h1s);
    cudaGetSymbolAddress((void**)&p_hs2, g_hs2);
    cudaGetSymbolAddress((void**)&p_g2,  g_g2);

    const int nscan = (n + SCAN_BLK - 1) / SCAN_BLK;   // 49

    // graph structure
    zero_kernel<<<(n + 255) / 256, 256>>>(n);
    deg_kernel<<<(E + 255) / 256, 256>>>(src, dst, E);
    scan1_kernel<<<nscan, SCAN_BLK>>>(n);   // also computes ns/nd
    scan2_kernel<<<1, MAX_SCAN_BLOCKS>>>(nscan);
    scan3_kernel<<<nscan, SCAN_BLK>>>(n);
    csr_fill_kernel<<<(E + 255) / 256, 256>>>(src, dst, E);

    // layer 1: h1s = (x @ W1) * ns   (M=n, N=128, K=256)
    gemm_kernel<128, 128, 16, 8, 8, true>
        <<<(n + 127) / 128, 256>>>(x, W1, p_h1s, n, hid, inf);
    agg1_kernel<<<(n + 7) / 8, 256>>>(b1, n);

    // layer 2: g2 = hs2 @ W2   (M=n, N=64, K=128); ns already baked into hs2
    gemm_kernel<128, 64, 16, 8, 4, false>
        <<<(n + 127) / 128, 256>>>(p_hs2, W2, p_g2, n, od, hid);
    agg2_kernel<<<(n + 7) / 8, 256>>>(b2, out, n);
}

// round 5
// speedup vs baseline: 1.2971x; 1.0965x over previous
#include <cuda_runtime.h>
#include <math.h>
#include <stdint.h>

// ---------------------------------------------------------------------------
// GNN_16535624089969: 2-layer GCN (DGL GraphConv norm='both')
//   N=50000, E=800000, dims 256 -> 128 -> 64, fp32.
// R4: tcgen05 unavailable (harness emits compute_103 PTX, no 'a' features).
//     Instead: packed fp32x2 FMA (fma.rn.f32x2, sm_100+ baseline PTX) in both
//     GEMM inner loops -> 2x fp32 FMA throughput. scan2 launch removed.
// ---------------------------------------------------------------------------

#define MAXN 50048
#define MAXE 800000
#define IN_DIM 256
#define HID_DIM 128
#define OUT_DIM 64
#define SCAN_BLK 1024
#define MAX_SCAN_BLOCKS 64

__device__ float g_h1s[50000 * HID_DIM];   // (x@W1) * norm_src
__device__ float g_hs2[50000 * HID_DIM];   // relu(agg1*nd+b1) * norm_src
__device__ float g_g2 [50000 * OUT_DIM];   // hs2 @ W2
__device__ int   g_csr_src[MAXE];
__device__ int   g_row_ptr[MAXN + 1];
__device__ int   g_cursor[MAXN];
__device__ int   g_outdeg[MAXN];
__device__ int   g_indeg[MAXN];
__device__ float g_ns[MAXN];
__device__ float g_nd[MAXN];
__device__ int   g_block_sums[MAX_SCAN_BLOCKS];

// ---------------------------------------------------------------------------
// packed f32x2 helpers (Blackwell, plain sm_100+ PTX -- no 'a' target needed)
// ---------------------------------------------------------------------------
__device__ __forceinline__ unsigned long long pack2(float x) {
    unsigned long long r;
    asm("mov.b64 %0, {%1, %1};" : "=l"(r) : "f"(x));
    return r;
}
__device__ __forceinline__ void ffma2(unsigned long long& d,
                                      unsigned long long a,
                                      unsigned long long b) {
    asm("fma.rn.f32x2 %0, %1, %2, %0;" : "+l"(d) : "l"(a), "l"(b));
}
__device__ __forceinline__ float2 unpack2(unsigned long long v) {
    float2 f;
    asm("mov.b64 {%0, %1}, %2;" : "=f"(f.x), "=f"(f.y) : "l"(v));
    return f;
}

// ---------------------------------------------------------------------------
// graph-structure kernels
// ---------------------------------------------------------------------------
__global__ void zero_kernel(int n) {
    int i = blockIdx.x * blockDim.x + threadIdx.x;
    if (i < n) { g_outdeg[i] = 0; g_indeg[i] = 0; g_cursor[i] = 0; }
}

__global__ void deg_kernel(const int* __restrict__ src,
                           const int* __restrict__ dst, int E) {
    int e = blockIdx.x * blockDim.x + threadIdx.x;
    if (e < E) {
        atomicAdd(&g_outdeg[src[e]], 1);
        atomicAdd(&g_indeg[dst[e]], 1);
    }
}

// per-block inclusive scan of indeg (warp shuffles); also computes ns/nd
__global__ __launch_bounds__(SCAN_BLK)
void scan1_kernel(int n) {
    int tid = threadIdx.x, i = blockIdx.x * SCAN_BLK + tid;
    int lane = tid & 31, w = tid >> 5;
    if (blockIdx.x == 0 && tid == 0) g_row_ptr[0] = 0;
    int indeg = 0;
    if (i < n) {
        indeg = g_indeg[i];
        g_ns[i] = rsqrtf(fmaxf((float)g_outdeg[i], 1.0f));
        g_nd[i] = rsqrtf(fmaxf((float)indeg, 1.0f));
    }
    int s = indeg;
#pragma unroll
    for (int d = 1; d < 32; d <<= 1) {
        int t = __shfl_up_sync(0xffffffffu, s, d);
        if (lane >= d) s += t;
    }
    __shared__ int wsum[32];
    if (lane == 31) wsum[w] = s;
    __syncthreads();
    if (w == 0) {
        int x = wsum[lane];
#pragma unroll
        for (int d = 1; d < 32; d <<= 1) {
            int t = __shfl_up_sync(0xffffffffu, x, d);
            if (lane >= d) x += t;
        }
        wsum[lane] = x;
    }
    __syncthreads();
    if (w > 0) s += wsum[w - 1];
    if (i < n) g_row_ptr[i + 1] = s;
    if (tid == SCAN_BLK - 1) g_block_sums[blockIdx.x] = s;
}

// add prefix of earlier block sums (<=63 values, warp reduction per block)
__global__ __launch_bounds__(SCAN_BLK)
void scan3_kernel(int n) {
    __shared__ int s_off;
    int bid = blockIdx.x;
    if (threadIdx.x < 32) {
        int acc = 0;
        for (int j = threadIdx.x; j < bid; j += 32) acc += g_block_sums[j];
#pragma unroll
        for (int d = 16; d; d >>= 1) acc += __shfl_down_sync(0xffffffffu, acc, d);
        if (threadIdx.x == 0) s_off = acc;
    }
    __syncthreads();
    int i = bid * SCAN_BLK + threadIdx.x;
    if (i < n) g_row_ptr[i + 1] += s_off;
}

__global__ void csr_fill_kernel(const int* __restrict__ src,
                                const int* __restrict__ dst, int E) {
    int e = blockIdx.x * blockDim.x + threadIdx.x;
    if (e < E) {
        int d = dst[e];
        int pos = g_row_ptr[d] + atomicAdd(&g_cursor[d], 1);
        g_csr_src[pos] = src[e];
    }
}

// ---------------------------------------------------------------------------
// Tiled fp32 GEMM with packed f32x2 FMA core.
// C[M,N] = A[M,K] @ B[K,N]; optional epilogue *= g_ns[row].
// 256 threads; (BM/TM)*(BN/TN) == 256; K % BK == 0; N == BN; TN % 4 == 0.
// ---------------------------------------------------------------------------
template <int BM, int BN, int BK, int TM, int TN, bool SCALE_NS>
__global__ __launch_bounds__(256)
void gemm_kernel(const float* __restrict__ A, const float* __restrict__ B,
                 float* __restrict__ C, int M, int N, int K) {
    __shared__ float As[BK][BM];
    __shared__ float Bs[BK][BN];

    const int tid = threadIdx.x;
    const int block_row = blockIdx.x * BM;
    constexpr int TCOLS = BN / TN;
    constexpr int TNP = TN / 2;               // f32x2 pairs
    const int tcol = tid % TCOLS;
    const int trow = tid / TCOLS;

    unsigned long long acc[TM][TNP];
#pragma unroll
    for (int i = 0; i < TM; i++)
#pragma unroll
        for (int j = 0; j < TNP; j++) acc[i][j] = 0ull;

    for (int k0 = 0; k0 < K; k0 += BK) {
        // load A tile (transposed into As[BK][BM]) via float4
#pragma unroll
        for (int i = tid; i < BM * BK / 4; i += 256) {
            int r  = i / (BK / 4);
            int c4 = i % (BK / 4);
            int grow = block_row + r;
            float4 v = make_float4(0.f, 0.f, 0.f, 0.f);
            if (grow < M)
                v = *(const float4*)&A[(size_t)grow * K + k0 + c4 * 4];
            As[c4 * 4 + 0][r] = v.x;
            As[c4 * 4 + 1][r] = v.y;
            As[c4 * 4 + 2][r] = v.z;
            As[c4 * 4 + 3][r] = v.w;
        }
        // load B tile
#pragma unroll
        for (int i = tid; i < BK * BN / 4; i += 256) {
            int r  = i / (BN / 4);
            int c4 = i % (BN / 4);
            *(float4*)&Bs[r][c4 * 4] =
                *(const float4*)&B[(size_t)(k0 + r) * N + c4 * 4];
        }
        __syncthreads();

#pragma unroll
        for (int k = 0; k < BK; k++) {
            // b pairs straight from shared (8B aligned)
            unsigned long long b2[TNP];
            const unsigned long long* bp =
                (const unsigned long long*)&Bs[k][tcol * TN];
#pragma unroll
            for (int j = 0; j < TNP; j++) b2[j] = bp[j];
            // a scalars, broadcast-packed
            const float4* ap = (const float4*)&As[k][trow * TM];
            unsigned long long a2[TM];
#pragma unroll
            for (int i4 = 0; i4 < TM / 4; i4++) {
                float4 av = ap[i4];
                a2[i4 * 4 + 0] = pack2(av.x);
                a2[i4 * 4 + 1] = pack2(av.y);
                a2[i4 * 4 + 2] = pack2(av.z);
                a2[i4 * 4 + 3] = pack2(av.w);
            }
#pragma unroll
            for (int i = 0; i < TM; i++)
#pragma unroll
                for (int j = 0; j < TNP; j++)
                    ffma2(acc[i][j], a2[i], b2[j]);
        }
        __syncthreads();
    }

#pragma unroll
    for (int i = 0; i < TM; i++) {
        int grow = block_row + trow * TM + i;
        if (grow >= M) continue;
        float s = 1.0f;
        if (SCALE_NS) s = g_ns[grow];
#pragma unroll
        for (int j4 = 0; j4 < TNP / 2; j4++) {
            float2 lo = unpack2(acc[i][j4 * 2 + 0]);
            float2 hi = unpack2(acc[i][j4 * 2 + 1]);
            float4 v;
            v.x = lo.x * s; v.y = lo.y * s;
            v.z = hi.x * s; v.w = hi.y * s;
            *(float4*)&C[(size_t)grow * N + tcol * TN + j4 * 4] = v;
        }
    }
}

// ---------------------------------------------------------------------------
// Layer-1 aggregation: warp per node over CSR, 128 feats = 32 lanes x float4.
// hs2[i] = relu(sum_j h1s[csr_src] * nd[i] + b1) * ns[i]
// ---------------------------------------------------------------------------
__global__ __launch_bounds__(256)
void agg1_kernel(const float* __restrict__ b1, int n) {
    int node = blockIdx.x * (blockDim.x >> 5) + (threadIdx.x >> 5);
    if (node >= n) return;
    int lane = threadIdx.x & 31;
    int s = g_row_ptr[node], e = g_row_ptr[node + 1];
    float4 acc = make_float4(0.f, 0.f, 0.f, 0.f);
#pragma unroll 4
    for (int j = s; j < e; j++) {
        int u = g_csr_src[j];
        float4 v = *(const float4*)&g_h1s[(size_t)u * HID_DIM + lane * 4];
        acc.x += v.x; acc.y += v.y; acc.z += v.z; acc.w += v.w;
    }
    float nd = g_nd[node], ns = g_ns[node];
    float4 bb = *(const float4*)&b1[lane * 4];
    float4 o;
    o.x = fmaxf(fmaf(acc.x, nd, bb.x), 0.f) * ns;
    o.y = fmaxf(fmaf(acc.y, nd, bb.y), 0.f) * ns;
    o.z = fmaxf(fmaf(acc.z, nd, bb.z), 0.f) * ns;
    o.w = fmaxf(fmaf(acc.w, nd, bb.w), 0.f) * ns;
    *(float4*)&g_hs2[(size_t)node * HID_DIM + lane * 4] = o;
}

// ---------------------------------------------------------------------------
// Layer-2 aggregation: warp per node, 64 feats = 32 lanes x float2.
// out[i] = sum_j g2[csr_src] * nd[i] + b2
// ---------------------------------------------------------------------------
__global__ __launch_bounds__(256)
void agg2_kernel(const float* __restrict__ b2, float* __restrict__ out, int n) {
    int node = blockIdx.x * (blockDim.x >> 5) + (threadIdx.x >> 5);
    if (node >= n) return;
    int lane = threadIdx.x & 31;
    int s = g_row_ptr[node], e = g_row_ptr[node + 1];
    float2 acc = make_float2(0.f, 0.f);
#pragma unroll 4
    for (int j = s; j < e; j++) {
        int u = g_csr_src[j];
        float2 v = *(const float2*)&g_g2[(size_t)u * OUT_DIM + lane * 2];
        acc.x += v.x; acc.y += v.y;
    }
    float nd = g_nd[node];
    float2 bb = *(const float2*)&b2[lane * 2];
    float2 o;
    o.x = fmaf(acc.x, nd, bb.x);
    o.y = fmaf(acc.y, nd, bb.y);
    *(float2*)&out[(size_t)node * OUT_DIM + lane * 2] = o;
}

// ---------------------------------------------------------------------------
extern "C" void kernel_launch(void* const* d_in, const int* in_sizes, int n_in,
                              void* d_out, int out_size) {
    const float* x   = (const float*)d_in[0];
    const float* W1  = (const float*)d_in[1];
    const float* b1  = (const float*)d_in[2];
    const float* W2  = (const float*)d_in[3];
    const float* b2  = (const float*)d_in[4];
    const int*   src = (const int*)d_in[5];
    const int*   dst = (const int*)d_in[6];
    float* out = (float*)d_out;

    const int n = in_sizes[0] / IN_DIM;      // 50000
    const int E = in_sizes[5];               // 800000

    float *p_h1s, *p_hs2, *p_g2;
    cudaGetSymbolAddress((void**)&p_h1s, g_h1s);
    cudaGetSymbolAddress((void**)&p_hs2, g_hs2);
    cudaGetSymbolAddress((void**)&p_g2,  g_g2);

    const int nscan = (n + SCAN_BLK - 1) / SCAN_BLK;     // 49

    // graph structure
    zero_kernel<<<(n + 255) / 256, 256>>>(n);
    deg_kernel<<<(E + 255) / 256, 256>>>(src, dst, E);
    scan1_kernel<<<nscan, SCAN_BLK>>>(n);
    scan3_kernel<<<nscan, SCAN_BLK>>>(n);
    csr_fill_kernel<<<(E + 255) / 256, 256>>>(src, dst, E);

    // layer 1: h1s = (x @ W1) * ns   (M=n, N=128, K=256)
    gemm_kernel<128, 128, 16, 8, 8, true>
        <<<(n + 127) / 128, 256>>>(x, W1, p_h1s, n, HID_DIM, IN_DIM);
    agg1_kernel<<<(n + 7) / 8, 256>>>(b1, n);

    // layer 2: g2 = hs2 @ W2   (M=n, N=64, K=128); ns baked into hs2
    gemm_kernel<128, 64, 16, 8, 4, false>
        <<<(n + 127) / 128, 256>>>(p_hs2, W2, p_g2, n, OUT_DIM, HID_DIM);
    agg2_kernel<<<(n + 7) / 8, 256>>>(b2, out, n);
}

// round 6
// speedup vs baseline: 1.3305x; 1.0257x over previous
#include <cuda_runtime.h>
#include <math.h>
#include <stdint.h>

// ---------------------------------------------------------------------------
// GNN_16535624089969: 2-layer GCN (DGL GraphConv norm='both')
//   N=50000, E=800000, dims 256 -> 128 -> 64, fp32.
// R5: - GEMM1 made independent of graph structure (ns multiply moved into
//       agg1 per-edge) and run on a FORKED STREAM concurrent with the
//       deg/scan/csr_fill chain (captured-graph fork/join via events).
//     - GEMM BK 16 -> 32 (half the syncthreads).
//     - f32x2 FMA core kept.
// ---------------------------------------------------------------------------

#define MAXN 50048
#define MAXE 800000
#define IN_DIM 256
#define HID_DIM 128
#define OUT_DIM 64
#define SCAN_BLK 1024
#define MAX_SCAN_BLOCKS 64

__device__ float g_h1[50000 * HID_DIM];    // x@W1 (no norm)
__device__ float g_hs2[50000 * HID_DIM];   // relu(agg1*nd+b1) * norm_src
__device__ float g_g2 [50000 * OUT_DIM];   // hs2 @ W2
__device__ int   g_csr_src[MAXE];
__device__ int   g_row_ptr[MAXN + 1];
__device__ int   g_cursor[MAXN];
__device__ int   g_outdeg[MAXN];
__device__ int   g_indeg[MAXN];
__device__ float g_ns[MAXN];
__device__ float g_nd[MAXN];
__device__ int   g_block_sums[MAX_SCAN_BLOCKS];

// ---------------------------------------------------------------------------
// packed f32x2 helpers (Blackwell, plain sm_100+ PTX)
// ---------------------------------------------------------------------------
__device__ __forceinline__ unsigned long long pack2(float x) {
    unsigned long long r;
    asm("mov.b64 %0, {%1, %1};" : "=l"(r) : "f"(x));
    return r;
}
__device__ __forceinline__ void ffma2(unsigned long long& d,
                                      unsigned long long a,
                                      unsigned long long b) {
    asm("fma.rn.f32x2 %0, %1, %2, %0;" : "+l"(d) : "l"(a), "l"(b));
}
__device__ __forceinline__ float2 unpack2(unsigned long long v) {
    float2 f;
    asm("mov.b64 {%0, %1}, %2;" : "=f"(f.x), "=f"(f.y) : "l"(v));
    return f;
}

// ---------------------------------------------------------------------------
// graph-structure kernels
// ---------------------------------------------------------------------------
__global__ void zero_kernel(int n) {
    int i = blockIdx.x * blockDim.x + threadIdx.x;
    if (i < n) { g_outdeg[i] = 0; g_indeg[i] = 0; g_cursor[i] = 0; }
}

__global__ void deg_kernel(const int* __restrict__ src,
                           const int* __restrict__ dst, int E) {
    int e = blockIdx.x * blockDim.x + threadIdx.x;
    if (e < E) {
        atomicAdd(&g_outdeg[src[e]], 1);
        atomicAdd(&g_indeg[dst[e]], 1);
    }
}

// per-block inclusive scan of indeg (warp shuffles); also computes ns/nd
__global__ __launch_bounds__(SCAN_BLK)
void scan1_kernel(int n) {
    int tid = threadIdx.x, i = blockIdx.x * SCAN_BLK + tid;
    int lane = tid & 31, w = tid >> 5;
    if (blockIdx.x == 0 && tid == 0) g_row_ptr[0] = 0;
    int indeg = 0;
    if (i < n) {
        indeg = g_indeg[i];
        g_ns[i] = rsqrtf(fmaxf((float)g_outdeg[i], 1.0f));
        g_nd[i] = rsqrtf(fmaxf((float)indeg, 1.0f));
    }
    int s = indeg;
#pragma unroll
    for (int d = 1; d < 32; d <<= 1) {
        int t = __shfl_up_sync(0xffffffffu, s, d);
        if (lane >= d) s += t;
    }
    __shared__ int wsum[32];
    if (lane == 31) wsum[w] = s;
    __syncthreads();
    if (w == 0) {
        int x = wsum[lane];
#pragma unroll
        for (int d = 1; d < 32; d <<= 1) {
            int t = __shfl_up_sync(0xffffffffu, x, d);
            if (lane >= d) x += t;
        }
        wsum[lane] = x;
    }
    __syncthreads();
    if (w > 0) s += wsum[w - 1];
    if (i < n) g_row_ptr[i + 1] = s;
    if (tid == SCAN_BLK - 1) g_block_sums[blockIdx.x] = s;
}

// add prefix of earlier block sums (<=63 values, warp reduction per block)
__global__ __launch_bounds__(SCAN_BLK)
void scan3_kernel(int n) {
    __shared__ int s_off;
    int bid = blockIdx.x;
    if (threadIdx.x < 32) {
        int acc = 0;
        for (int j = threadIdx.x; j < bid; j += 32) acc += g_block_sums[j];
#pragma unroll
        for (int d = 16; d; d >>= 1) acc += __shfl_down_sync(0xffffffffu, acc, d);
        if (threadIdx.x == 0) s_off = acc;
    }
    __syncthreads();
    int i = bid * SCAN_BLK + threadIdx.x;
    if (i < n) g_row_ptr[i + 1] += s_off;
}

__global__ void csr_fill_kernel(const int* __restrict__ src,
                                const int* __restrict__ dst, int E) {
    int e = blockIdx.x * blockDim.x + threadIdx.x;
    if (e < E) {
        int d = dst[e];
        int pos = g_row_ptr[d] + atomicAdd(&g_cursor[d], 1);
        g_csr_src[pos] = src[e];
    }
}

// ---------------------------------------------------------------------------
// Tiled fp32 GEMM with packed f32x2 FMA core.
// C[M,N] = A[M,K] @ B[K,N].
// 256 threads; (BM/TM)*(BN/TN) == 256; K % BK == 0; N == BN; TN % 4 == 0.
// ---------------------------------------------------------------------------
template <int BM, int BN, int BK, int TM, int TN>
__global__ __launch_bounds__(256)
void gemm_kernel(const float* __restrict__ A, const float* __restrict__ B,
                 float* __restrict__ C, int M, int N, int K) {
    __shared__ float As[BK][BM];
    __shared__ float Bs[BK][BN];

    const int tid = threadIdx.x;
    const int block_row = blockIdx.x * BM;
    constexpr int TCOLS = BN / TN;
    constexpr int TNP = TN / 2;               // f32x2 pairs
    const int tcol = tid % TCOLS;
    const int trow = tid / TCOLS;

    unsigned long long acc[TM][TNP];
#pragma unroll
    for (int i = 0; i < TM; i++)
#pragma unroll
        for (int j = 0; j < TNP; j++) acc[i][j] = 0ull;

    for (int k0 = 0; k0 < K; k0 += BK) {
        // load A tile (transposed into As[BK][BM]) via float4
#pragma unroll
        for (int i = tid; i < BM * BK / 4; i += 256) {
            int r  = i / (BK / 4);
            int c4 = i % (BK / 4);
            int grow = block_row + r;
            float4 v = make_float4(0.f, 0.f, 0.f, 0.f);
            if (grow < M)
                v = *(const float4*)&A[(size_t)grow * K + k0 + c4 * 4];
            As[c4 * 4 + 0][r] = v.x;
            As[c4 * 4 + 1][r] = v.y;
            As[c4 * 4 + 2][r] = v.z;
            As[c4 * 4 + 3][r] = v.w;
        }
        // load B tile
#pragma unroll
        for (int i = tid; i < BK * BN / 4; i += 256) {
            int r  = i / (BN / 4);
            int c4 = i % (BN / 4);
            *(float4*)&Bs[r][c4 * 4] =
                *(const float4*)&B[(size_t)(k0 + r) * N + c4 * 4];
        }
        __syncthreads();

#pragma unroll
        for (int k = 0; k < BK; k++) {
            unsigned long long b2[TNP];
            const unsigned long long* bp =
                (const unsigned long long*)&Bs[k][tcol * TN];
#pragma unroll
            for (int j = 0; j < TNP; j++) b2[j] = bp[j];
            const float4* ap = (const float4*)&As[k][trow * TM];
            unsigned long long a2[TM];
#pragma unroll
            for (int i4 = 0; i4 < TM / 4; i4++) {
                float4 av = ap[i4];
                a2[i4 * 4 + 0] = pack2(av.x);
                a2[i4 * 4 + 1] = pack2(av.y);
                a2[i4 * 4 + 2] = pack2(av.z);
                a2[i4 * 4 + 3] = pack2(av.w);
            }
#pragma unroll
            for (int i = 0; i < TM; i++)
#pragma unroll
                for (int j = 0; j < TNP; j++)
                    ffma2(acc[i][j], a2[i], b2[j]);
        }
        __syncthreads();
    }

#pragma unroll
    for (int i = 0; i < TM; i++) {
        int grow = block_row + trow * TM + i;
        if (grow >= M) continue;
#pragma unroll
        for (int j4 = 0; j4 < TNP / 2; j4++) {
            float2 lo = unpack2(acc[i][j4 * 2 + 0]);
            float2 hi = unpack2(acc[i][j4 * 2 + 1]);
            float4 v;
            v.x = lo.x; v.y = lo.y;
            v.z = hi.x; v.w = hi.y;
            *(float4*)&C[(size_t)grow * N + tcol * TN + j4 * 4] = v;
        }
    }
}

// ---------------------------------------------------------------------------
// Layer-1 aggregation: warp per node over CSR, 128 feats = 32 lanes x float4.
// hs2[i] = relu((sum_j h1[u_j]*ns[u_j]) * nd[i] + b1) * ns[i]
// (ns[u] applied per-edge so GEMM1 has no dependence on graph structure)
// ---------------------------------------------------------------------------
__global__ __launch_bounds__(256)
void agg1_kernel(const float* __restrict__ b1, int n) {
    int node = blockIdx.x * (blockDim.x >> 5) + (threadIdx.x >> 5);
    if (node >= n) return;
    int lane = threadIdx.x & 31;
    int s = g_row_ptr[node], e = g_row_ptr[node + 1];
    float4 acc = make_float4(0.f, 0.f, 0.f, 0.f);
#pragma unroll 4
    for (int j = s; j < e; j++) {
        int u = g_csr_src[j];
        float nsu = __ldg(&g_ns[u]);
        float4 v = *(const float4*)&g_h1[(size_t)u * HID_DIM + lane * 4];
        acc.x = fmaf(v.x, nsu, acc.x);
        acc.y = fmaf(v.y, nsu, acc.y);
        acc.z = fmaf(v.z, nsu, acc.z);
        acc.w = fmaf(v.w, nsu, acc.w);
    }
    float nd = g_nd[node], ns = g_ns[node];
    float4 bb = *(const float4*)&b1[lane * 4];
    float4 o;
    o.x = fmaxf(fmaf(acc.x, nd, bb.x), 0.f) * ns;
    o.y = fmaxf(fmaf(acc.y, nd, bb.y), 0.f) * ns;
    o.z = fmaxf(fmaf(acc.z, nd, bb.z), 0.f) * ns;
    o.w = fmaxf(fmaf(acc.w, nd, bb.w), 0.f) * ns;
    *(float4*)&g_hs2[(size_t)node * HID_DIM + lane * 4] = o;
}

// ---------------------------------------------------------------------------
// Layer-2 aggregation: warp per node, 64 feats = 32 lanes x float2.
// out[i] = sum_j g2[csr_src] * nd[i] + b2   (ns baked into hs2)
// ---------------------------------------------------------------------------
__global__ __launch_bounds__(256)
void agg2_kernel(const float* __restrict__ b2, float* __restrict__ out, int n) {
    int node = blockIdx.x * (blockDim.x >> 5) + (threadIdx.x >> 5);
    if (node >= n) return;
    int lane = threadIdx.x & 31;
    int s = g_row_ptr[node], e = g_row_ptr[node + 1];
    float2 acc = make_float2(0.f, 0.f);
#pragma unroll 4
    for (int j = s; j < e; j++) {
        int u = g_csr_src[j];
        float2 v = *(const float2*)&g_g2[(size_t)u * OUT_DIM + lane * 2];
        acc.x += v.x; acc.y += v.y;
    }
    float nd = g_nd[node];
    float2 bb = *(const float2*)&b2[lane * 2];
    float2 o;
    o.x = fmaf(acc.x, nd, bb.x);
    o.y = fmaf(acc.y, nd, bb.y);
    *(float2*)&out[(size_t)node * OUT_DIM + lane * 2] = o;
}

// ---------------------------------------------------------------------------
extern "C" void kernel_launch(void* const* d_in, const int* in_sizes, int n_in,
                              void* d_out, int out_size) {
    const float* x   = (const float*)d_in[0];
    const float* W1  = (const float*)d_in[1];
    const float* b1  = (const float*)d_in[2];
    const float* W2  = (const float*)d_in[3];
    const float* b2  = (const float*)d_in[4];
    const int*   src = (const int*)d_in[5];
    const int*   dst = (const int*)d_in[6];
    float* out = (float*)d_out;

    const int n = in_sizes[0] / IN_DIM;      // 50000
    const int E = in_sizes[5];               // 800000

    float *p_h1, *p_hs2, *p_g2;
    cudaGetSymbolAddress((void**)&p_h1,  g_h1);
    cudaGetSymbolAddress((void**)&p_hs2, g_hs2);
    cudaGetSymbolAddress((void**)&p_g2,  g_g2);

    const int nscan = (n + SCAN_BLK - 1) / SCAN_BLK;     // 49

    // fork: GEMM1 (depends only on x, W1) runs concurrently with the
    // graph-structure chain. Host-side stream/event creation only (no device
    // memory); works both live and under stream capture.
    cudaStream_t s2;
    cudaStreamCreate(&s2);
    cudaEvent_t e_fork, e_join;
    cudaEventCreateWithFlags(&e_fork, cudaEventDisableTiming);
    cudaEventCreateWithFlags(&e_join, cudaEventDisableTiming);

    cudaEventRecord(e_fork, 0);
    cudaStreamWaitEvent(s2, e_fork, 0);

    // side stream: layer-1 GEMM  h1 = x @ W1   (M=n, N=128, K=256)
    gemm_kernel<128, 128, 32, 8, 8>
        <<<(n + 127) / 128, 256, 0, s2>>>(x, W1, p_h1, n, HID_DIM, IN_DIM);
    cudaEventRecord(e_join, s2);

    // main stream: graph structure
    zero_kernel<<<(n + 255) / 256, 256>>>(n);
    deg_kernel<<<(E + 255) / 256, 256>>>(src, dst, E);
    scan1_kernel<<<nscan, SCAN_BLK>>>(n);
    scan3_kernel<<<nscan, SCAN_BLK>>>(n);
    csr_fill_kernel<<<(E + 255) / 256, 256>>>(src, dst, E);

    // join, then the serial tail
    cudaStreamWaitEvent(0, e_join, 0);
    agg1_kernel<<<(n + 7) / 8, 256>>>(b1, n);
    gemm_kernel<128, 64, 32, 8, 4>
        <<<(n + 127) / 128, 256>>>(p_hs2, W2, p_g2, n, OUT_DIM, HID_DIM);
    agg2_kernel<<<(n + 7) / 8, 256>>>(b2, out, n);
}

// round 7
// speedup vs baseline: 1.7807x; 1.3383x over previous
#include <cuda_runtime.h>
#include <math.h>
#include <stdint.h>

// ---------------------------------------------------------------------------
// GNN_16535624089969: 2-layer GCN (DGL GraphConv norm='both')
//   N=50000, E=800000, dims 256 -> 128 -> 64, fp32.
// R6: - GEMM1 -> mma.sync m16n8k16 bf16 (baseline PTX, Blackwell HMMA) with
//       bf16 hi/lo 3-split for fp32-grade accuracy (~1e-5).
//     - GEMM2 keeps f32x2 core, gains As padding (kills 8-way STS conflicts).
//     - fork/join overlap of GEMM1 with graph-structure chain retained.
// ---------------------------------------------------------------------------

#define MAXN 50048
#define MAXE 800000
#define IN_DIM 256
#define HID_DIM 128
#define OUT_DIM 64
#define SCAN_BLK 1024
#define MAX_SCAN_BLOCKS 64

__device__ float g_h1[50000 * HID_DIM];    // x@W1 (no norm)
__device__ float g_hs2[50000 * HID_DIM];   // relu(agg1*nd+b1) * norm_src
__device__ float g_g2 [50000 * OUT_DIM];   // hs2 @ W2
__device__ int   g_csr_src[MAXE];
__device__ int   g_row_ptr[MAXN + 1];
__device__ int   g_cursor[MAXN];
__device__ int   g_outdeg[MAXN];
__device__ int   g_indeg[MAXN];
__device__ float g_ns[MAXN];
__device__ float g_nd[MAXN];
__device__ int   g_block_sums[MAX_SCAN_BLOCKS];

// ---------------------------------------------------------------------------
// helpers
// ---------------------------------------------------------------------------
__device__ __forceinline__ unsigned long long pack2(float x) {
    unsigned long long r;
    asm("mov.b64 %0, {%1, %1};" : "=l"(r) : "f"(x));
    return r;
}
__device__ __forceinline__ void ffma2(unsigned long long& d,
                                      unsigned long long a,
                                      unsigned long long b) {
    asm("fma.rn.f32x2 %0, %1, %2, %0;" : "+l"(d) : "l"(a), "l"(b));
}
__device__ __forceinline__ float2 unpack2(unsigned long long v) {
    float2 f;
    asm("mov.b64 {%0, %1}, %2;" : "=f"(f.x), "=f"(f.y) : "l"(v));
    return f;
}

// bf16 hi/lo split of an fp32 value (round-to-nearest each stage)
__device__ __forceinline__ void splitbf(float v, unsigned short& h,
                                        unsigned short& l) {
    unsigned short hh;
    float hf;
    asm("cvt.rn.bf16.f32 %0, %1;" : "=h"(hh) : "f"(v));
    asm("mov.b32 %0, {0, %1};" : "=f"(hf) : "h"(hh));  // bf16 -> f32 (hi bits)
    float r = v - hf;
    unsigned short ll;
    asm("cvt.rn.bf16.f32 %0, %1;" : "=h"(ll) : "f"(r));
    h = hh; l = ll;
}

// mma.sync m16n8k16 row.col f32.bf16.bf16.f32 (sm_80+ baseline PTX)
__device__ __forceinline__ void mma16816(float* c, const uint32_t* a,
                                         const uint32_t* b) {
    asm volatile(
        "mma.sync.aligned.m16n8k16.row.col.f32.bf16.bf16.f32 "
        "{%0,%1,%2,%3}, {%4,%5,%6,%7}, {%8,%9}, {%0,%1,%2,%3};"
        : "+f"(c[0]), "+f"(c[1]), "+f"(c[2]), "+f"(c[3])
        : "r"(a[0]), "r"(a[1]), "r"(a[2]), "r"(a[3]), "r"(b[0]), "r"(b[1]));
}

// ---------------------------------------------------------------------------
// graph-structure kernels (unchanged)
// ---------------------------------------------------------------------------
__global__ void zero_kernel(int n) {
    int i = blockIdx.x * blockDim.x + threadIdx.x;
    if (i < n) { g_outdeg[i] = 0; g_indeg[i] = 0; g_cursor[i] = 0; }
}

__global__ void deg_kernel(const int* __restrict__ src,
                           const int* __restrict__ dst, int E) {
    int e = blockIdx.x * blockDim.x + threadIdx.x;
    if (e < E) {
        atomicAdd(&g_outdeg[src[e]], 1);
        atomicAdd(&g_indeg[dst[e]], 1);
    }
}

__global__ __launch_bounds__(SCAN_BLK)
void scan1_kernel(int n) {
    int tid = threadIdx.x, i = blockIdx.x * SCAN_BLK + tid;
    int lane = tid & 31, w = tid >> 5;
    if (blockIdx.x == 0 && tid == 0) g_row_ptr[0] = 0;
    int indeg = 0;
    if (i < n) {
        indeg = g_indeg[i];
        g_ns[i] = rsqrtf(fmaxf((float)g_outdeg[i], 1.0f));
        g_nd[i] = rsqrtf(fmaxf((float)indeg, 1.0f));
    }
    int s = indeg;
#pragma unroll
    for (int d = 1; d < 32; d <<= 1) {
        int t = __shfl_up_sync(0xffffffffu, s, d);
        if (lane >= d) s += t;
    }
    __shared__ int wsum[32];
    if (lane == 31) wsum[w] = s;
    __syncthreads();
    if (w == 0) {
        int x = wsum[lane];
#pragma unroll
        for (int d = 1; d < 32; d <<= 1) {
            int t = __shfl_up_sync(0xffffffffu, x, d);
            if (lane >= d) x += t;
        }
        wsum[lane] = x;
    }
    __syncthreads();
    if (w > 0) s += wsum[w - 1];
    if (i < n) g_row_ptr[i + 1] = s;
    if (tid == SCAN_BLK - 1) g_block_sums[blockIdx.x] = s;
}

__global__ __launch_bounds__(SCAN_BLK)
void scan3_kernel(int n) {
    __shared__ int s_off;
    int bid = blockIdx.x;
    if (threadIdx.x < 32) {
        int acc = 0;
        for (int j = threadIdx.x; j < bid; j += 32) acc += g_block_sums[j];
#pragma unroll
        for (int d = 16; d; d >>= 1) acc += __shfl_down_sync(0xffffffffu, acc, d);
        if (threadIdx.x == 0) s_off = acc;
    }
    __syncthreads();
    int i = bid * SCAN_BLK + threadIdx.x;
    if (i < n) g_row_ptr[i + 1] += s_off;
}

__global__ void csr_fill_kernel(const int* __restrict__ src,
                                const int* __restrict__ dst, int E) {
    int e = blockIdx.x * blockDim.x + threadIdx.x;
    if (e < E) {
        int d = dst[e];
        int pos = g_row_ptr[d] + atomicAdd(&g_cursor[d], 1);
        g_csr_src[pos] = src[e];
    }
}

// ---------------------------------------------------------------------------
// GEMM1 via mma.sync bf16 3-split: C[M,128] = A[M,256] @ W[256,128]
// CTA: 256 thr, tile 128x128. Warp tile 64x32 (mt 0..3, nt 0..3).
// SMEM: k-major bf16 hi/lo tiles, row stride 36 elems (pad vs conflicts).
// ---------------------------------------------------------------------------
#define SROW 36

__global__ __launch_bounds__(256)
void gemm1_mma_kernel(const float* __restrict__ A, const float* __restrict__ W,
                      float* __restrict__ C, int M) {
    __shared__ __align__(16) unsigned short sAh[128 * SROW];
    __shared__ __align__(16) unsigned short sAl[128 * SROW];
    __shared__ __align__(16) unsigned short sBh[128 * SROW];
    __shared__ __align__(16) unsigned short sBl[128 * SROW];

    const int tid = threadIdx.x;
    const int lane = tid & 31, wid = tid >> 5;
    const int g = lane >> 2, t = lane & 3;
    const int warp_m = (wid & 1) * 64;     // {0,64}
    const int warp_n = (wid >> 1) * 32;    // {0,32,64,96}
    const int block_row = blockIdx.x * 128;

    float acc[4][4][4];
#pragma unroll
    for (int i = 0; i < 4; i++)
#pragma unroll
        for (int j = 0; j < 4; j++)
#pragma unroll
            for (int q = 0; q < 4; q++) acc[i][j][q] = 0.0f;

    const int lr = tid >> 1;          // 0..127 (A row / B col)
    const int lk = tid & 1;           // k half (0..15 / 16..31)

    for (int k0 = 0; k0 < IN_DIM; k0 += 32) {
        // ---- A tile: 128 rows x 32 k, fp32 -> bf16 hi/lo, k-major ----
        {
            int grow = block_row + lr;
            float v[16];
            if (grow < M) {
                const float4* ap =
                    (const float4*)&A[(size_t)grow * IN_DIM + k0 + lk * 16];
#pragma unroll
                for (int j = 0; j < 4; j++) {
                    float4 f = ap[j];
                    v[j * 4 + 0] = f.x; v[j * 4 + 1] = f.y;
                    v[j * 4 + 2] = f.z; v[j * 4 + 3] = f.w;
                }
            } else {
#pragma unroll
                for (int j = 0; j < 16; j++) v[j] = 0.0f;
            }
            unsigned short h[16], l[16];
#pragma unroll
            for (int j = 0; j < 16; j++) splitbf(v[j], h[j], l[j]);
            int base = lr * SROW + lk * 16;
#pragma unroll
            for (int j = 0; j < 4; j++) {
                uint2 ph = make_uint2(
                    (uint32_t)h[j*4+0] | ((uint32_t)h[j*4+1] << 16),
                    (uint32_t)h[j*4+2] | ((uint32_t)h[j*4+3] << 16));
                uint2 pl = make_uint2(
                    (uint32_t)l[j*4+0] | ((uint32_t)l[j*4+1] << 16),
                    (uint32_t)l[j*4+2] | ((uint32_t)l[j*4+3] << 16));
                *(uint2*)&sAh[base + j * 4] = ph;
                *(uint2*)&sAl[base + j * 4] = pl;
            }
        }
        // ---- B tile: W rows k0..k0+31, cols 0..127 -> sB[n][k] ----
        {
            int n = lr;
            const float* wp = &W[(size_t)(k0 + lk * 16) * HID_DIM + n];
            unsigned short h[16], l[16];
#pragma unroll
            for (int j = 0; j < 16; j++)
                splitbf(wp[j * HID_DIM], h[j], l[j]);
            int base = n * SROW + lk * 16;
#pragma unroll
            for (int j = 0; j < 4; j++) {
                uint2 ph = make_uint2(
                    (uint32_t)h[j*4+0] | ((uint32_t)h[j*4+1] << 16),
                    (uint32_t)h[j*4+2] | ((uint32_t)h[j*4+3] << 16));
                uint2 pl = make_uint2(
                    (uint32_t)l[j*4+0] | ((uint32_t)l[j*4+1] << 16),
                    (uint32_t)l[j*4+2] | ((uint32_t)l[j*4+3] << 16));
                *(uint2*)&sBh[base + j * 4] = ph;
                *(uint2*)&sBl[base + j * 4] = pl;
            }
        }
        __syncthreads();

#pragma unroll
        for (int kk = 0; kk < 32; kk += 16) {
            uint32_t ah[4][4], al[4][4];
#pragma unroll
            for (int mt = 0; mt < 4; mt++) {
                int row = warp_m + mt * 16 + g;
                int b0 = row * SROW + kk + 2 * t;
                ah[mt][0] = *(const uint32_t*)&sAh[b0];
                ah[mt][1] = *(const uint32_t*)&sAh[b0 + 8 * SROW];
                ah[mt][2] = *(const uint32_t*)&sAh[b0 + 8];
                ah[mt][3] = *(const uint32_t*)&sAh[b0 + 8 * SROW + 8];
                al[mt][0] = *(const uint32_t*)&sAl[b0];
                al[mt][1] = *(const uint32_t*)&sAl[b0 + 8 * SROW];
                al[mt][2] = *(const uint32_t*)&sAl[b0 + 8];
                al[mt][3] = *(const uint32_t*)&sAl[b0 + 8 * SROW + 8];
            }
            uint32_t bh[4][2], bl[4][2];
#pragma unroll
            for (int nt = 0; nt < 4; nt++) {
                int nr = warp_n + nt * 8 + g;
                int b0 = nr * SROW + kk + 2 * t;
                bh[nt][0] = *(const uint32_t*)&sBh[b0];
                bh[nt][1] = *(const uint32_t*)&sBh[b0 + 8];
                bl[nt][0] = *(const uint32_t*)&sBl[b0];
                bl[nt][1] = *(const uint32_t*)&sBl[b0 + 8];
            }
#pragma unroll
            for (int mt = 0; mt < 4; mt++)
#pragma unroll
                for (int nt = 0; nt < 4; nt++) {
                    mma16816(acc[mt][nt], ah[mt], bh[nt]);
                    mma16816(acc[mt][nt], al[mt], bh[nt]);
                    mma16816(acc[mt][nt], ah[mt], bl[nt]);
                }
        }
        __syncthreads();
    }

    // epilogue: c0,c1 -> C[row][col..col+1]; c2,c3 -> C[row+8][...]
#pragma unroll
    for (int mt = 0; mt < 4; mt++) {
        int row = block_row + warp_m + mt * 16 + g;
#pragma unroll
        for (int nt = 0; nt < 4; nt++) {
            int col = warp_n + nt * 8 + 2 * t;
            if (row < M)
                *(float2*)&C[(size_t)row * HID_DIM + col] =
                    make_float2(acc[mt][nt][0], acc[mt][nt][1]);
            if (row + 8 < M)
                *(float2*)&C[(size_t)(row + 8) * HID_DIM + col] =
                    make_float2(acc[mt][nt][2], acc[mt][nt][3]);
        }
    }
}

// ---------------------------------------------------------------------------
// f32x2 GEMM (layer 2). As padded +4 to kill transpose-store conflicts.
// ---------------------------------------------------------------------------
template <int BM, int BN, int BK, int TM, int TN>
__global__ __launch_bounds__(256)
void gemm_kernel(const float* __restrict__ A, const float* __restrict__ B,
                 float* __restrict__ C, int M, int N, int K) {
    __shared__ float As[BK][BM + 4];
    __shared__ float Bs[BK][BN];

    const int tid = threadIdx.x;
    const int block_row = blockIdx.x * BM;
    constexpr int TCOLS = BN / TN;
    constexpr int TNP = TN / 2;
    const int tcol = tid % TCOLS;
    const int trow = tid / TCOLS;

    unsigned long long acc[TM][TNP];
#pragma unroll
    for (int i = 0; i < TM; i++)
#pragma unroll
        for (int j = 0; j < TNP; j++) acc[i][j] = 0ull;

    for (int k0 = 0; k0 < K; k0 += BK) {
#pragma unroll
        for (int i = tid; i < BM * BK / 4; i += 256) {
            int r  = i / (BK / 4);
            int c4 = i % (BK / 4);
            int grow = block_row + r;
            float4 v = make_float4(0.f, 0.f, 0.f, 0.f);
            if (grow < M)
                v = *(const float4*)&A[(size_t)grow * K + k0 + c4 * 4];
            As[c4 * 4 + 0][r] = v.x;
            As[c4 * 4 + 1][r] = v.y;
            As[c4 * 4 + 2][r] = v.z;
            As[c4 * 4 + 3][r] = v.w;
        }
#pragma unroll
        for (int i = tid; i < BK * BN / 4; i += 256) {
            int r  = i / (BN / 4);
            int c4 = i % (BN / 4);
            *(float4*)&Bs[r][c4 * 4] =
                *(const float4*)&B[(size_t)(k0 + r) * N + c4 * 4];
        }
        __syncthreads();

#pragma unroll
        for (int k = 0; k < BK; k++) {
            unsigned long long b2[TNP];
            const unsigned long long* bp =
                (const unsigned long long*)&Bs[k][tcol * TN];
#pragma unroll
            for (int j = 0; j < TNP; j++) b2[j] = bp[j];
            const float4* ap = (const float4*)&As[k][trow * TM];
            unsigned long long a2[TM];
#pragma unroll
            for (int i4 = 0; i4 < TM / 4; i4++) {
                float4 av = ap[i4];
                a2[i4 * 4 + 0] = pack2(av.x);
                a2[i4 * 4 + 1] = pack2(av.y);
                a2[i4 * 4 + 2] = pack2(av.z);
                a2[i4 * 4 + 3] = pack2(av.w);
            }
#pragma unroll
            for (int i = 0; i < TM; i++)
#pragma unroll
                for (int j = 0; j < TNP; j++)
                    ffma2(acc[i][j], a2[i], b2[j]);
        }
        __syncthreads();
    }

#pragma unroll
    for (int i = 0; i < TM; i++) {
        int grow = block_row + trow * TM + i;
        if (grow >= M) continue;
#pragma unroll
        for (int j4 = 0; j4 < TNP / 2; j4++) {
            float2 lo = unpack2(acc[i][j4 * 2 + 0]);
            float2 hi = unpack2(acc[i][j4 * 2 + 1]);
            float4 v;
            v.x = lo.x; v.y = lo.y;
            v.z = hi.x; v.w = hi.y;
            *(float4*)&C[(size_t)grow * N + tcol * TN + j4 * 4] = v;
        }
    }
}

// ---------------------------------------------------------------------------
// aggregation (unchanged from R6)
// ---------------------------------------------------------------------------
__global__ __launch_bounds__(256)
void agg1_kernel(const float* __restrict__ b1, int n) {
    int node = blockIdx.x * (blockDim.x >> 5) + (threadIdx.x >> 5);
    if (node >= n) return;
    int lane = threadIdx.x & 31;
    int s = g_row_ptr[node], e = g_row_ptr[node + 1];
    float4 acc = make_float4(0.f, 0.f, 0.f, 0.f);
#pragma unroll 4
    for (int j = s; j < e; j++) {
        int u = g_csr_src[j];
        float nsu = __ldg(&g_ns[u]);
        float4 v = *(const float4*)&g_h1[(size_t)u * HID_DIM + lane * 4];
        acc.x = fmaf(v.x, nsu, acc.x);
        acc.y = fmaf(v.y, nsu, acc.y);
        acc.z = fmaf(v.z, nsu, acc.z);
        acc.w = fmaf(v.w, nsu, acc.w);
    }
    float nd = g_nd[node], ns = g_ns[node];
    float4 bb = *(const float4*)&b1[lane * 4];
    float4 o;
    o.x = fmaxf(fmaf(acc.x, nd, bb.x), 0.f) * ns;
    o.y = fmaxf(fmaf(acc.y, nd, bb.y), 0.f) * ns;
    o.z = fmaxf(fmaf(acc.z, nd, bb.z), 0.f) * ns;
    o.w = fmaxf(fmaf(acc.w, nd, bb.w), 0.f) * ns;
    *(float4*)&g_hs2[(size_t)node * HID_DIM + lane * 4] = o;
}

__global__ __launch_bounds__(256)
void agg2_kernel(const float* __restrict__ b2, float* __restrict__ out, int n) {
    int node = blockIdx.x * (blockDim.x >> 5) + (threadIdx.x >> 5);
    if (node >= n) return;
    int lane = threadIdx.x & 31;
    int s = g_row_ptr[node], e = g_row_ptr[node + 1];
    float2 acc = make_float2(0.f, 0.f);
#pragma unroll 4
    for (int j = s; j < e; j++) {
        int u = g_csr_src[j];
        float2 v = *(const float2*)&g_g2[(size_t)u * OUT_DIM + lane * 2];
        acc.x += v.x; acc.y += v.y;
    }
    float nd = g_nd[node];
    float2 bb = *(const float2*)&b2[lane * 2];
    float2 o;
    o.x = fmaf(acc.x, nd, bb.x);
    o.y = fmaf(acc.y, nd, bb.y);
    *(float2*)&out[(size_t)node * OUT_DIM + lane * 2] = o;
}

// ---------------------------------------------------------------------------
extern "C" void kernel_launch(void* const* d_in, const int* in_sizes, int n_in,
                              void* d_out, int out_size) {
    const float* x   = (const float*)d_in[0];
    const float* W1  = (const float*)d_in[1];
    const float* b1  = (const float*)d_in[2];
    const float* W2  = (const float*)d_in[3];
    const float* b2  = (const float*)d_in[4];
    const int*   src = (const int*)d_in[5];
    const int*   dst = (const int*)d_in[6];
    float* out = (float*)d_out;

    const int n = in_sizes[0] / IN_DIM;      // 50000
    const int E = in_sizes[5];               // 800000

    float *p_h1, *p_hs2, *p_g2;
    cudaGetSymbolAddress((void**)&p_h1,  g_h1);
    cudaGetSymbolAddress((void**)&p_hs2, g_hs2);
    cudaGetSymbolAddress((void**)&p_g2,  g_g2);

    const int nscan = (n + SCAN_BLK - 1) / SCAN_BLK;     // 49

    // fork: GEMM1 (depends only on x, W1) concurrent with structure chain.
    cudaStream_t s2;
    cudaStreamCreate(&s2);
    cudaEvent_t e_fork, e_join;
    cudaEventCreateWithFlags(&e_fork, cudaEventDisableTiming);
    cudaEventCreateWithFlags(&e_join, cudaEventDisableTiming);

    cudaEventRecord(e_fork, 0);
    cudaStreamWaitEvent(s2, e_fork, 0);

    gemm1_mma_kernel<<<(n + 127) / 128, 256, 0, s2>>>(x, W1, p_h1, n);
    cudaEventRecord(e_join, s2);

    zero_kernel<<<(n + 255) / 256, 256>>>(n);
    deg_kernel<<<(E + 255) / 256, 256>>>(src, dst, E);
    scan1_kernel<<<nscan, SCAN_BLK>>>(n);
    scan3_kernel<<<nscan, SCAN_BLK>>>(n);
    csr_fill_kernel<<<(E + 255) / 256, 256>>>(src, dst, E);

    cudaStreamWaitEvent(0, e_join, 0);
    agg1_kernel<<<(n + 7) / 8, 256>>>(b1, n);
    gemm_kernel<128, 64, 32, 8, 4>
        <<<(n + 127) / 128, 256>>>(p_hs2, W2, p_g2, n, OUT_DIM, HID_DIM);
    agg2_kernel<<<(n + 7) / 8, 256>>>(b2, out, n);
}